// round 3
// baseline (speedup 1.0000x reference)
#include <cuda_runtime.h>

#define HID 64
#define EXT 32
#define TE 64
#define TN 64
#define MAX_NODES 50000

// Per-node precomputed partials (already multiplied through W2a):
//   g_P[n] = h[n] @ (W1a @ W2a),  g_Q[n] = h[n] @ (W1c @ W2a)
__device__ float g_P[MAX_NODES * HID];
__device__ float g_Q[MAX_NODES * HID];
// Fused weights
__device__ float g_W12[HID * HID];   // W1b @ W2a
__device__ float g_Wa2[HID * HID];   // W1a @ W2a
__device__ float g_Wc2[HID * HID];   // W1c @ W2a
__device__ float g_b12[HID];         // b1 @ W2a + b2

typedef unsigned long long u64;

__device__ __forceinline__ u64 pk2(float x, float y) {
    u64 r; asm("mov.b64 %0,{%1,%2};" : "=l"(r) : "f"(x), "f"(y)); return r;
}
__device__ __forceinline__ float2 up2(u64 v) {
    float2 f; asm("mov.b64 {%0,%1},%2;" : "=f"(f.x), "=f"(f.y) : "l"(v)); return f;
}
__device__ __forceinline__ void ffma2(u64& d, u64 a, u64 b) {
    asm("fma.rn.f32x2 %0,%1,%2,%0;" : "+l"(d) : "l"(a), "l"(b));
}

// ---------------------------------------------------------------------------
// Kernel 0: fold W2a into W1 parts and biases.
// ---------------------------------------------------------------------------
__global__ __launch_bounds__(256) void combo_kernel(
    const float* __restrict__ W1, const float* __restrict__ b1,
    const float* __restrict__ W2, const float* __restrict__ b2)
{
    __shared__ float W2s[HID * HID];
    for (int i = threadIdx.x; i < HID * HID; i += 256) W2s[i] = W2[i];
    __syncthreads();

    int b = blockIdx.x;
    if (b < 12) {
        int mat = b >> 2;
        const float* srcW = W1 + (size_t)mat * HID * HID;
        float* dstW = (mat == 0) ? g_Wa2 : (mat == 1) ? g_W12 : g_Wc2;
        int row = (b & 3) * 16 + (threadIdx.x >> 4);
        int c0 = (threadIdx.x & 15) * 4;
        float4 a = make_float4(0.f, 0.f, 0.f, 0.f);
        #pragma unroll 8
        for (int k = 0; k < HID; k++) {
            float s = srcW[row * HID + k];
            float4 w = *(const float4*)(W2s + k * HID + c0);
            a.x = fmaf(s, w.x, a.x); a.y = fmaf(s, w.y, a.y);
            a.z = fmaf(s, w.z, a.z); a.w = fmaf(s, w.w, a.w);
        }
        *(float4*)(dstW + row * HID + c0) = a;
    } else {
        if (threadIdx.x < HID) {
            int o = threadIdx.x;
            float acc = b2[o];
            #pragma unroll 8
            for (int k = 0; k < HID; k++)
                acc = fmaf(b1[k], W2s[k * HID + o], acc);
            g_b12[o] = acc;
        }
    }
}

// ---------------------------------------------------------------------------
// Kernel 1: per-node  P = h @ Wa2,  Q = h @ Wc2
// ---------------------------------------------------------------------------
#define NODE_SMEM_BYTES ((4096 + 4096 + HID * TN) * 4)

__global__ __launch_bounds__(256) void node_pre(const float* __restrict__ h,
                                                int n_nodes)
{
    extern __shared__ float sm[];
    float* Wa  = sm;
    float* Wc  = Wa + 4096;
    float* hst = Wc + 4096;            // [k][r], stride TN

    for (int i = threadIdx.x; i < HID * HID; i += 256) {
        Wa[i] = g_Wa2[i];
        Wc[i] = g_Wc2[i];
    }

    const int tx = threadIdx.x & 15;
    const int ty = threadIdx.x >> 4;
    const int j0 = tx * 4;
    const int r0 = ty * 4;
    const int ntiles = (n_nodes + TN - 1) / TN;

    for (int tile = blockIdx.x; tile < ntiles; tile += gridDim.x) {
        const int base = tile * TN;
        __syncthreads();
        for (int idx = threadIdx.x; idx < (HID / 4) * TN; idx += 256) {
            int cq = idx >> 6;
            int r  = idx & (TN - 1);
            int node = base + r;
            float4 v = make_float4(0.f, 0.f, 0.f, 0.f);
            if (node < n_nodes) v = *(const float4*)(h + (size_t)node * HID + cq * 4);
            hst[(cq * 4 + 0) * TN + r] = v.x;
            hst[(cq * 4 + 1) * TN + r] = v.y;
            hst[(cq * 4 + 2) * TN + r] = v.z;
            hst[(cq * 4 + 3) * TN + r] = v.w;
        }
        __syncthreads();

        u64 aP[4][2], aQ[4][2];
        #pragma unroll
        for (int j = 0; j < 4; j++) {
            aP[j][0] = aP[j][1] = 0ULL;
            aQ[j][0] = aQ[j][1] = 0ULL;
        }
        #pragma unroll 4
        for (int k = 0; k < HID; k++) {
            ulonglong2 sv = *(const ulonglong2*)(hst + k * TN + r0);
            float4 wa = *(const float4*)(Wa + k * HID + j0);
            float4 wc = *(const float4*)(Wc + k * HID + j0);
            u64 a0 = pk2(wa.x, wa.x), a1 = pk2(wa.y, wa.y),
                a2 = pk2(wa.z, wa.z), a3 = pk2(wa.w, wa.w);
            u64 c0 = pk2(wc.x, wc.x), c1 = pk2(wc.y, wc.y),
                c2 = pk2(wc.z, wc.z), c3 = pk2(wc.w, wc.w);
            ffma2(aP[0][0], a0, sv.x); ffma2(aP[0][1], a0, sv.y);
            ffma2(aP[1][0], a1, sv.x); ffma2(aP[1][1], a1, sv.y);
            ffma2(aP[2][0], a2, sv.x); ffma2(aP[2][1], a2, sv.y);
            ffma2(aP[3][0], a3, sv.x); ffma2(aP[3][1], a3, sv.y);
            ffma2(aQ[0][0], c0, sv.x); ffma2(aQ[0][1], c0, sv.y);
            ffma2(aQ[1][0], c1, sv.x); ffma2(aQ[1][1], c1, sv.y);
            ffma2(aQ[2][0], c2, sv.x); ffma2(aQ[2][1], c2, sv.y);
            ffma2(aQ[3][0], c3, sv.x); ffma2(aQ[3][1], c3, sv.y);
        }
        #pragma unroll
        for (int r = 0; r < 4; r++) {
            int node = base + r0 + r;
            if (node < n_nodes) {
                float4 p, q; float2 c;
                c = up2(aP[0][r >> 1]); p.x = (r & 1) ? c.y : c.x;
                c = up2(aP[1][r >> 1]); p.y = (r & 1) ? c.y : c.x;
                c = up2(aP[2][r >> 1]); p.z = (r & 1) ? c.y : c.x;
                c = up2(aP[3][r >> 1]); p.w = (r & 1) ? c.y : c.x;
                c = up2(aQ[0][r >> 1]); q.x = (r & 1) ? c.y : c.x;
                c = up2(aQ[1][r >> 1]); q.y = (r & 1) ? c.y : c.x;
                c = up2(aQ[2][r >> 1]); q.z = (r & 1) ? c.y : c.x;
                c = up2(aQ[3][r >> 1]); q.w = (r & 1) ? c.y : c.x;
                *(float4*)(g_P + (size_t)node * HID + j0) = p;
                *(float4*)(g_Q + (size_t)node * HID + j0) = q;
            }
        }
    }
}

// ---------------------------------------------------------------------------
// Kernel 2: per-edge  out = relu( P[src] + Q[dst] + e_h@W12 + ext@W2b + b12 )
// ---------------------------------------------------------------------------
#define EDGE_SMEM_FLOATS (4096 + 2048 + 64 + HID * TE + EXT * TE)
#define EDGE_SMEM_BYTES  (EDGE_SMEM_FLOATS * 4 + TE * 2 * 4)

__global__ __launch_bounds__(256) void edge_kernel(
    const float* __restrict__ e_h,
    const float* __restrict__ ext,
    const float* __restrict__ W2,
    const int* __restrict__ src,
    const int* __restrict__ dst,
    float* __restrict__ out,
    int n_edges)
{
    extern __shared__ float sm[];
    float* W12s = sm;
    float* W2bs = W12s + 4096;
    float* b12s = W2bs + 2048;
    float* ehs  = b12s + 64;           // [k][r] stride TE
    float* exts = ehs + HID * TE;      // [k][r] stride TE
    int*   srcs = (int*)(exts + EXT * TE);
    int*   dsts = srcs + TE;

    for (int i = threadIdx.x; i < HID * HID; i += 256) W12s[i] = g_W12[i];
    for (int i = threadIdx.x; i < EXT * HID; i += 256) W2bs[i] = W2[HID * HID + i];
    if (threadIdx.x < HID) b12s[threadIdx.x] = g_b12[threadIdx.x];

    const int tx = threadIdx.x & 15;
    const int ty = threadIdx.x >> 4;
    const int j0 = tx * 4;
    const int r0 = ty * 4;
    const int ntiles = (n_edges + TE - 1) / TE;

    for (int tile = blockIdx.x; tile < ntiles; tile += gridDim.x) {
        const int base = tile * TE;
        __syncthreads();

        for (int idx = threadIdx.x; idx < (HID / 4) * TE; idx += 256) {
            int cq = idx >> 6;
            int r  = idx & (TE - 1);
            int e = base + r;
            float4 v = make_float4(0.f, 0.f, 0.f, 0.f);
            if (e < n_edges) v = *(const float4*)(e_h + (size_t)e * HID + cq * 4);
            ehs[(cq * 4 + 0) * TE + r] = v.x;
            ehs[(cq * 4 + 1) * TE + r] = v.y;
            ehs[(cq * 4 + 2) * TE + r] = v.z;
            ehs[(cq * 4 + 3) * TE + r] = v.w;
        }
        for (int idx = threadIdx.x; idx < (EXT / 4) * TE; idx += 256) {
            int cq = idx >> 6;
            int r  = idx & (TE - 1);
            int e = base + r;
            float4 v = make_float4(0.f, 0.f, 0.f, 0.f);
            if (e < n_edges) v = *(const float4*)(ext + (size_t)e * EXT + cq * 4);
            exts[(cq * 4 + 0) * TE + r] = v.x;
            exts[(cq * 4 + 1) * TE + r] = v.y;
            exts[(cq * 4 + 2) * TE + r] = v.z;
            exts[(cq * 4 + 3) * TE + r] = v.w;
        }
        if (threadIdx.x < TE) {
            int e = base + threadIdx.x;
            srcs[threadIdx.x] = (e < n_edges) ? src[e] : 0;
            dsts[threadIdx.x] = (e < n_edges) ? dst[e] : 0;
        }
        __syncthreads();

        float4 bv = *(const float4*)(b12s + j0);
        float4 pq[4];
        #pragma unroll
        for (int r = 0; r < 4; r++) {
            float4 p = *(const float4*)(g_P + (size_t)srcs[r0 + r] * HID + j0);
            float4 q = *(const float4*)(g_Q + (size_t)dsts[r0 + r] * HID + j0);
            pq[r].x = p.x + q.x + bv.x;
            pq[r].y = p.y + q.y + bv.y;
            pq[r].z = p.z + q.z + bv.z;
            pq[r].w = p.w + q.w + bv.w;
        }

        u64 acc[4][2];
        #pragma unroll
        for (int j = 0; j < 4; j++) acc[j][0] = acc[j][1] = 0ULL;

        #pragma unroll 8
        for (int k = 0; k < HID; k++) {
            ulonglong2 sv = *(const ulonglong2*)(ehs + k * TE + r0);
            float4 w = *(const float4*)(W12s + k * HID + j0);
            u64 w0 = pk2(w.x, w.x), w1 = pk2(w.y, w.y),
                w2 = pk2(w.z, w.z), w3 = pk2(w.w, w.w);
            ffma2(acc[0][0], w0, sv.x); ffma2(acc[0][1], w0, sv.y);
            ffma2(acc[1][0], w1, sv.x); ffma2(acc[1][1], w1, sv.y);
            ffma2(acc[2][0], w2, sv.x); ffma2(acc[2][1], w2, sv.y);
            ffma2(acc[3][0], w3, sv.x); ffma2(acc[3][1], w3, sv.y);
        }
        #pragma unroll 8
        for (int k = 0; k < EXT; k++) {
            ulonglong2 sv = *(const ulonglong2*)(exts + k * TE + r0);
            float4 w = *(const float4*)(W2bs + k * HID + j0);
            u64 w0 = pk2(w.x, w.x), w1 = pk2(w.y, w.y),
                w2 = pk2(w.z, w.z), w3 = pk2(w.w, w.w);
            ffma2(acc[0][0], w0, sv.x); ffma2(acc[0][1], w0, sv.y);
            ffma2(acc[1][0], w1, sv.x); ffma2(acc[1][1], w1, sv.y);
            ffma2(acc[2][0], w2, sv.x); ffma2(acc[2][1], w2, sv.y);
            ffma2(acc[3][0], w3, sv.x); ffma2(acc[3][1], w3, sv.y);
        }

        #pragma unroll
        for (int r = 0; r < 4; r++) {
            int e = base + r0 + r;
            if (e < n_edges) {
                float2 c0 = up2(acc[0][r >> 1]);
                float2 c1 = up2(acc[1][r >> 1]);
                float2 c2 = up2(acc[2][r >> 1]);
                float2 c3 = up2(acc[3][r >> 1]);
                float4 o;
                o.x = fmaxf(((r & 1) ? c0.y : c0.x) + pq[r].x, 0.f);
                o.y = fmaxf(((r & 1) ? c1.y : c1.x) + pq[r].y, 0.f);
                o.z = fmaxf(((r & 1) ? c2.y : c2.x) + pq[r].z, 0.f);
                o.w = fmaxf(((r & 1) ? c3.y : c3.x) + pq[r].w, 0.f);
                *(float4*)(out + (size_t)e * HID + j0) = o;
            }
        }
    }
}

// ---------------------------------------------------------------------------
extern "C" void kernel_launch(void* const* d_in, const int* in_sizes, int n_in,
                              void* d_out, int out_size)
{
    const float* h   = (const float*)d_in[0];
    const float* e_h = (const float*)d_in[1];
    const float* ext = (const float*)d_in[2];
    const float* W1  = (const float*)d_in[3];
    const float* b1  = (const float*)d_in[4];
    const float* W2  = (const float*)d_in[5];
    const float* b2  = (const float*)d_in[6];
    const int*   src = (const int*)d_in[7];
    const int*   dst = (const int*)d_in[8];
    float* out = (float*)d_out;

    int n_nodes = in_sizes[0] / HID;
    int n_edges = in_sizes[7];

    cudaFuncSetAttribute(node_pre, cudaFuncAttributeMaxDynamicSharedMemorySize,
                         NODE_SMEM_BYTES);
    cudaFuncSetAttribute(edge_kernel, cudaFuncAttributeMaxDynamicSharedMemorySize,
                         EDGE_SMEM_BYTES);

    combo_kernel<<<13, 256>>>(W1, b1, W2, b2);

    int node_tiles = (n_nodes + TN - 1) / TN;
    int grid1 = node_tiles < 592 ? node_tiles : 592;
    node_pre<<<grid1, 256, NODE_SMEM_BYTES>>>(h, n_nodes);

    int edge_tiles = (n_edges + TE - 1) / TE;
    int grid2 = edge_tiles < 592 ? edge_tiles : 592;
    edge_kernel<<<grid2, 256, EDGE_SMEM_BYTES>>>(e_h, ext, W2, src, dst, out,
                                                 n_edges);
}

// round 9
// speedup vs baseline: 1.3006x; 1.3006x over previous
#include <cuda_runtime.h>
#include <cstdint>

#define HID 64
#define EXT 32
#define TN 64
#define TM 128          // edges per tile
#define MAX_NODES 50000

// ---------------------------------------------------------------------------
// Globals
// ---------------------------------------------------------------------------
__device__ float g_P[MAX_NODES * HID];        // h @ (W1a@W2a)
__device__ float g_Q[MAX_NODES * HID];        // h @ (W1c@W2a) + b12 (bias baked in)
__device__ float g_W12[HID * HID];            // W1b @ W2a (fp32)
__device__ float g_Wa2[HID * HID];
__device__ float g_Wc2[HID * HID];
__device__ float g_b12[HID];                  // b1 @ W2a + b2
// Split bf16 weights, packed as bf16x2 per k-pair: g_Bp[kp][n], kp = k/2.
// kp [0:32)=W12_hi [32:64)=W12_lo [64:80)=W2b_hi [80:96)=W2b_lo
__device__ unsigned g_Bp[96 * 64];

typedef unsigned long long u64;

// Single extern shared declaration for all kernels
extern __shared__ __align__(16) unsigned char smraw[];

// ---------------------------------------------------------------------------
// Helpers
// ---------------------------------------------------------------------------
__device__ __forceinline__ u64 pk2(float x, float y) {
    u64 r; asm("mov.b64 %0,{%1,%2};" : "=l"(r) : "f"(x), "f"(y)); return r;
}
__device__ __forceinline__ float2 up2(u64 v) {
    float2 f; asm("mov.b64 {%0,%1},%2;" : "=f"(f.x), "=f"(f.y) : "l"(v)); return f;
}
__device__ __forceinline__ void ffma2(u64& d, u64 a, u64 b) {
    asm("fma.rn.f32x2 %0,%1,%2,%0;" : "+l"(d) : "l"(a), "l"(b));
}
// bf16 hi/lo split of two floats, packed as bf16x2 words (x0 -> low half)
__device__ __forceinline__ void split2(float x0, float x1, unsigned& hi, unsigned& lo) {
    unsigned h;
    asm("cvt.rn.bf16x2.f32 %0, %1, %2;" : "=r"(h) : "f"(x1), "f"(x0));
    float h0 = __uint_as_float(h << 16);
    float h1 = __uint_as_float(h & 0xFFFF0000u);
    float l0 = x0 - h0, l1 = x1 - h1;
    unsigned l;
    asm("cvt.rn.bf16x2.f32 %0, %1, %2;" : "=r"(l) : "f"(l1), "f"(l0));
    hi = h; lo = l;
}
__device__ __forceinline__ void mma16816(float* c, uint4 a, unsigned b0, unsigned b1) {
    asm volatile(
        "mma.sync.aligned.m16n8k16.row.col.f32.bf16.bf16.f32 "
        "{%0,%1,%2,%3},{%4,%5,%6,%7},{%8,%9},{%0,%1,%2,%3};"
        : "+f"(c[0]), "+f"(c[1]), "+f"(c[2]), "+f"(c[3])
        : "r"(a.x), "r"(a.y), "r"(a.z), "r"(a.w), "r"(b0), "r"(b1));
}

// Fragment-linear A smem address for element (row r, k-pair kp).
// Frag block (mt,kt) is 32 lanes x 16B; within 16B: regs a0..a3.
__device__ __forceinline__ unsigned frag_addr(int r, int kp) {
    int mt = r >> 4, rr = r & 15;
    int kt = kp >> 3, kk = kp & 7;
    int lane = ((rr & 7) << 2) + (kk & 3);
    int reg  = (rr >> 3) + ((kk >> 2) << 1);
    return (unsigned)(((((mt * 12 + kt) << 5) + lane) << 4) + (reg << 2));
}

// ---------------------------------------------------------------------------
// Kernel 0a: fold W2a into W1 parts + bias.  grid 49 x 256
// ---------------------------------------------------------------------------
__global__ __launch_bounds__(256) void combo_kernel(
    const float* __restrict__ W1, const float* __restrict__ b1,
    const float* __restrict__ W2, const float* __restrict__ b2)
{
    __shared__ float W2s[HID * HID];
    __shared__ float rW[256];
    for (int i = threadIdx.x; i < HID * HID; i += 256) W2s[i] = W2[i];

    int b = blockIdx.x;
    if (b < 48) {
        int mat = b >> 4, rb = b & 15;
        rW[threadIdx.x] = W1[(size_t)mat * HID * HID + rb * 256 + threadIdx.x];
        __syncthreads();
        int lr = threadIdx.x >> 6, col = threadIdx.x & 63;
        float acc = 0.f;
        #pragma unroll 8
        for (int k = 0; k < HID; k++)
            acc = fmaf(rW[lr * HID + k], W2s[k * HID + col], acc);
        float* dstW = (mat == 0) ? g_Wa2 : (mat == 1) ? g_W12 : g_Wc2;
        dstW[(rb * 4 + lr) * HID + col] = acc;
    } else {
        __syncthreads();
        if (threadIdx.x < HID) {
            float acc = b2[threadIdx.x];
            #pragma unroll 8
            for (int k = 0; k < HID; k++)
                acc = fmaf(b1[k], W2s[k * HID + threadIdx.x], acc);
            g_b12[threadIdx.x] = acc;
        }
    }
}

// ---------------------------------------------------------------------------
// Kernel 0b: build split bf16x2 weight blob.  grid 1 x 256
// ---------------------------------------------------------------------------
__global__ __launch_bounds__(256) void build_B(const float* __restrict__ W2)
{
    for (int idx = threadIdx.x; idx < 48 * 64; idx += 256) {
        int kp = idx >> 6, n = idx & 63;
        float x0, x1;
        int hi_kp, lo_kp;
        if (kp < 32) {
            x0 = g_W12[(2 * kp) * HID + n];
            x1 = g_W12[(2 * kp + 1) * HID + n];
            hi_kp = kp; lo_kp = 32 + kp;
        } else {
            int ks = kp - 32;
            x0 = W2[(size_t)(HID + 2 * ks) * HID + n];
            x1 = W2[(size_t)(HID + 2 * ks + 1) * HID + n];
            hi_kp = 64 + ks; lo_kp = 80 + ks;
        }
        unsigned hi, lo;
        split2(x0, x1, hi, lo);
        g_Bp[hi_kp * 64 + n] = hi;
        g_Bp[lo_kp * 64 + n] = lo;
    }
}

// ---------------------------------------------------------------------------
// Kernel 1: per-node  P = h @ Wa2 ; Q = h @ Wc2 + b12   (FFMA2)
// ---------------------------------------------------------------------------
#define NODE_SMEM_BYTES ((4096 + 4096 + HID * TN) * 4)

__global__ __launch_bounds__(256) void node_pre(const float* __restrict__ h,
                                                int n_nodes)
{
    float* sm  = (float*)smraw;
    float* Wa  = sm;
    float* Wc  = Wa + 4096;
    float* hst = Wc + 4096;

    for (int i = threadIdx.x; i < HID * HID; i += 256) {
        Wa[i] = g_Wa2[i];
        Wc[i] = g_Wc2[i];
    }

    const int tx = threadIdx.x & 15;
    const int ty = threadIdx.x >> 4;
    const int j0 = tx * 4;
    const int r0 = ty * 4;
    const int ntiles = (n_nodes + TN - 1) / TN;

    float4 bv = *(const float4*)(g_b12 + j0);
    u64 qb0 = pk2(bv.x, bv.x), qb1 = pk2(bv.y, bv.y),
        qb2 = pk2(bv.z, bv.z), qb3 = pk2(bv.w, bv.w);

    for (int tile = blockIdx.x; tile < ntiles; tile += gridDim.x) {
        const int base = tile * TN;
        __syncthreads();
        for (int idx = threadIdx.x; idx < (HID / 4) * TN; idx += 256) {
            int cq = idx >> 6;
            int r  = idx & (TN - 1);
            int node = base + r;
            float4 v = make_float4(0.f, 0.f, 0.f, 0.f);
            if (node < n_nodes) v = *(const float4*)(h + (size_t)node * HID + cq * 4);
            hst[(cq * 4 + 0) * TN + r] = v.x;
            hst[(cq * 4 + 1) * TN + r] = v.y;
            hst[(cq * 4 + 2) * TN + r] = v.z;
            hst[(cq * 4 + 3) * TN + r] = v.w;
        }
        __syncthreads();

        u64 aP[4][2], aQ[4][2];
        #pragma unroll
        for (int j = 0; j < 4; j++) aP[j][0] = aP[j][1] = 0ULL;
        aQ[0][0] = aQ[0][1] = qb0;
        aQ[1][0] = aQ[1][1] = qb1;
        aQ[2][0] = aQ[2][1] = qb2;
        aQ[3][0] = aQ[3][1] = qb3;

        #pragma unroll 4
        for (int k = 0; k < HID; k++) {
            ulonglong2 sv = *(const ulonglong2*)(hst + k * TN + r0);
            float4 wa = *(const float4*)(Wa + k * HID + j0);
            float4 wc = *(const float4*)(Wc + k * HID + j0);
            u64 a0 = pk2(wa.x, wa.x), a1 = pk2(wa.y, wa.y),
                a2 = pk2(wa.z, wa.z), a3 = pk2(wa.w, wa.w);
            u64 c0 = pk2(wc.x, wc.x), c1 = pk2(wc.y, wc.y),
                c2 = pk2(wc.z, wc.z), c3 = pk2(wc.w, wc.w);
            ffma2(aP[0][0], a0, sv.x); ffma2(aP[0][1], a0, sv.y);
            ffma2(aP[1][0], a1, sv.x); ffma2(aP[1][1], a1, sv.y);
            ffma2(aP[2][0], a2, sv.x); ffma2(aP[2][1], a2, sv.y);
            ffma2(aP[3][0], a3, sv.x); ffma2(aP[3][1], a3, sv.y);
            ffma2(aQ[0][0], c0, sv.x); ffma2(aQ[0][1], c0, sv.y);
            ffma2(aQ[1][0], c1, sv.x); ffma2(aQ[1][1], c1, sv.y);
            ffma2(aQ[2][0], c2, sv.x); ffma2(aQ[2][1], c2, sv.y);
            ffma2(aQ[3][0], c3, sv.x); ffma2(aQ[3][1], c3, sv.y);
        }
        #pragma unroll
        for (int r = 0; r < 4; r++) {
            int node = base + r0 + r;
            if (node < n_nodes) {
                float4 p, q; float2 c;
                c = up2(aP[0][r >> 1]); p.x = (r & 1) ? c.y : c.x;
                c = up2(aP[1][r >> 1]); p.y = (r & 1) ? c.y : c.x;
                c = up2(aP[2][r >> 1]); p.z = (r & 1) ? c.y : c.x;
                c = up2(aP[3][r >> 1]); p.w = (r & 1) ? c.y : c.x;
                c = up2(aQ[0][r >> 1]); q.x = (r & 1) ? c.y : c.x;
                c = up2(aQ[1][r >> 1]); q.y = (r & 1) ? c.y : c.x;
                c = up2(aQ[2][r >> 1]); q.z = (r & 1) ? c.y : c.x;
                c = up2(aQ[3][r >> 1]); q.w = (r & 1) ? c.y : c.x;
                *(float4*)(g_P + (size_t)node * HID + j0) = p;
                *(float4*)(g_Q + (size_t)node * HID + j0) = q;
            }
        }
    }
}

// ---------------------------------------------------------------------------
// Kernel 2: per-edge via mma.sync (HMMA bf16, correct 3-term split)
//   A (smem) kt blocks: 0-3 eh_hi | 4-7 eh_lo | 8-9 ext_hi | 10-11 ext_lo
//   Main B:  kt0-7 -> W12_hi, kt8-11 -> W2b_hi   (hi*hi + lo*hi)
//   Cross B: kt0-3 -> W12_lo, kt8-9 -> W2b_lo    (hi*lo, reusing A frags)
//   out = relu( sum + P[src] + Q[dst] )
// ---------------------------------------------------------------------------
#define A_BYTES (8 * 12 * 32 * 16)      // 49152
#define OFF_SRC A_BYTES
#define OFF_DST (OFF_SRC + TM * 4)
#define EDGE_SMEM_BYTES (OFF_DST + TM * 4)

__global__ __launch_bounds__(256) void edge_kernel(
    const float* __restrict__ e_h,
    const float* __restrict__ ext,
    const int* __restrict__ src,
    const int* __restrict__ dst,
    float* __restrict__ out,
    int n_edges)
{
    unsigned char* A = smraw;
    int* srcs = (int*)(smraw + OFF_SRC);
    int* dsts = (int*)(smraw + OFF_DST);

    const int tid = threadIdx.x;
    const int w = tid >> 5, lane = tid & 31;
    const int n0 = w * 8;
    const int lr = lane >> 2;            // 0..7
    const int lc = lane & 3;             // 0..3

    // ---- B fragments (registers, live whole kernel) ----
    // Main pass: bm[kt], kt 0..11
    unsigned bm0[12], bm1[12];
    #pragma unroll
    for (int kt = 0; kt < 8; kt++) {               // A = eh_hi (0-3), eh_lo (4-7) -> W12_hi
        int kp = (kt & 3) * 8 + lc;                // W12_hi region [0:32)
        bm0[kt] = g_Bp[kp * 64 + n0 + lr];
        bm1[kt] = g_Bp[(kp + 4) * 64 + n0 + lr];
    }
    #pragma unroll
    for (int kt = 8; kt < 12; kt++) {              // A = ext_hi (8-9), ext_lo (10-11) -> W2b_hi
        int kp = 64 + ((kt - 8) & 1) * 8 + lc;     // W2b_hi region [64:80)
        bm0[kt] = g_Bp[kp * 64 + n0 + lr];
        bm1[kt] = g_Bp[(kp + 4) * 64 + n0 + lr];
    }
    // Cross pass: bc[j], j 0..3 -> W12_lo (A kt j), j 4..5 -> W2b_lo (A kt 8+j-4)
    unsigned bc0[6], bc1[6];
    #pragma unroll
    for (int j = 0; j < 4; j++) {
        int kp = 32 + j * 8 + lc;                  // W12_lo region [32:64)
        bc0[j] = g_Bp[kp * 64 + n0 + lr];
        bc1[j] = g_Bp[(kp + 4) * 64 + n0 + lr];
    }
    #pragma unroll
    for (int j = 4; j < 6; j++) {
        int kp = 80 + (j - 4) * 8 + lc;            // W2b_lo region [80:96)
        bc0[j] = g_Bp[kp * 64 + n0 + lr];
        bc1[j] = g_Bp[(kp + 4) * 64 + n0 + lr];
    }

    const int ntiles = (n_edges + TM - 1) / TM;

    for (int tile = blockIdx.x; tile < ntiles; tile += gridDim.x) {
        const int base = tile * TM;
        __syncthreads();   // previous tile fully consumed before A overwrite

        // ---- stage e_h: hi -> kt 0-3 (kp c4/2), lo -> kt 4-7 (kp 32+c4/2) ----
        for (int idx = tid; idx < TM * 16; idx += 256) {
            int r = idx >> 4, c4 = (idx & 15) << 2;
            int e = base + r;
            float4 v = (e < n_edges) ? *(const float4*)(e_h + (size_t)e * HID + c4)
                                     : make_float4(0.f, 0.f, 0.f, 0.f);
            unsigned h01, l01, h23, l23;
            split2(v.x, v.y, h01, l01);
            split2(v.z, v.w, h23, l23);
            int kp = c4 >> 1;
            *(unsigned*)(A + frag_addr(r, kp))          = h01;
            *(unsigned*)(A + frag_addr(r, kp + 1))      = h23;
            *(unsigned*)(A + frag_addr(r, 32 + kp))     = l01;
            *(unsigned*)(A + frag_addr(r, 32 + kp + 1)) = l23;
        }
        // ---- stage ext: hi -> kt 8-9 (kp 64+c4/2), lo -> kt 10-11 (kp 80+c4/2) ----
        for (int idx = tid; idx < TM * 8; idx += 256) {
            int r = idx >> 3, c4 = (idx & 7) << 2;
            int e = base + r;
            float4 v = (e < n_edges) ? *(const float4*)(ext + (size_t)e * EXT + c4)
                                     : make_float4(0.f, 0.f, 0.f, 0.f);
            unsigned h01, l01, h23, l23;
            split2(v.x, v.y, h01, l01);
            split2(v.z, v.w, h23, l23);
            int kp = c4 >> 1;
            *(unsigned*)(A + frag_addr(r, 64 + kp))     = h01;
            *(unsigned*)(A + frag_addr(r, 64 + kp + 1)) = h23;
            *(unsigned*)(A + frag_addr(r, 80 + kp))     = l01;
            *(unsigned*)(A + frag_addr(r, 80 + kp + 1)) = l23;
        }
        if (tid < TM) {
            int e = base + tid;
            srcs[tid] = (e < n_edges) ? src[e] : 0;
            dsts[tid] = (e < n_edges) ? dst[e] : 0;
        }
        __syncthreads();

        // ---- 8 m-tiles: 12 main + 6 cross MMAs each (A frags reused) ----
        float acc[8][4];
        #pragma unroll
        for (int mt = 0; mt < 8; mt++) {
            acc[mt][0] = acc[mt][1] = acc[mt][2] = acc[mt][3] = 0.f;
            const uint4* Ab = (const uint4*)(A) + (mt * 12) * 32 + lane;
            #pragma unroll
            for (int kt = 0; kt < 12; kt++) {
                uint4 a = Ab[kt * 32];
                mma16816(acc[mt], a, bm0[kt], bm1[kt]);
                if (kt < 4)
                    mma16816(acc[mt], a, bc0[kt], bc1[kt]);      // eh_hi x W12_lo
                else if (kt == 8 || kt == 9)
                    mma16816(acc[mt], a, bc0[kt - 4], bc1[kt - 4]); // ext_hi x W2b_lo
            }
        }

        // ---- epilogue: relu(acc + P[src] + Q[dst]) ----
        const int c = n0 + lc * 2;
        #pragma unroll
        for (int mt = 0; mt < 8; mt++) {
            int r1 = mt * 16 + lr, r2 = r1 + 8;
            int e1 = base + r1, e2 = base + r2;
            if (e1 < n_edges) {
                float2 p = *(const float2*)(g_P + (size_t)srcs[r1] * HID + c);
                float2 q = *(const float2*)(g_Q + (size_t)dsts[r1] * HID + c);
                float2 o;
                o.x = fmaxf(acc[mt][0] + p.x + q.x, 0.f);
                o.y = fmaxf(acc[mt][1] + p.y + q.y, 0.f);
                *(float2*)(out + (size_t)e1 * HID + c) = o;
            }
            if (e2 < n_edges) {
                float2 p = *(const float2*)(g_P + (size_t)srcs[r2] * HID + c);
                float2 q = *(const float2*)(g_Q + (size_t)dsts[r2] * HID + c);
                float2 o;
                o.x = fmaxf(acc[mt][2] + p.x + q.x, 0.f);
                o.y = fmaxf(acc[mt][3] + p.y + q.y, 0.f);
                *(float2*)(out + (size_t)e2 * HID + c) = o;
            }
        }
    }
}

// ---------------------------------------------------------------------------
extern "C" void kernel_launch(void* const* d_in, const int* in_sizes, int n_in,
                              void* d_out, int out_size)
{
    const float* h   = (const float*)d_in[0];
    const float* e_h = (const float*)d_in[1];
    const float* ext = (const float*)d_in[2];
    const float* W1  = (const float*)d_in[3];
    const float* b1  = (const float*)d_in[4];
    const float* W2  = (const float*)d_in[5];
    const float* b2  = (const float*)d_in[6];
    const int*   src = (const int*)d_in[7];
    const int*   dst = (const int*)d_in[8];
    float* out = (float*)d_out;

    int n_nodes = in_sizes[0] / HID;
    int n_edges = in_sizes[7];

    cudaFuncSetAttribute(node_pre, cudaFuncAttributeMaxDynamicSharedMemorySize,
                         NODE_SMEM_BYTES);
    cudaFuncSetAttribute(edge_kernel, cudaFuncAttributeMaxDynamicSharedMemorySize,
                         EDGE_SMEM_BYTES);

    combo_kernel<<<49, 256>>>(W1, b1, W2, b2);
    build_B<<<1, 256>>>(W2);

    int node_tiles = (n_nodes + TN - 1) / TN;
    int grid1 = node_tiles < 592 ? node_tiles : 592;
    node_pre<<<grid1, 256, NODE_SMEM_BYTES>>>(h, n_nodes);

    int edge_tiles = (n_edges + TM - 1) / TM;
    int grid2 = edge_tiles < 444 ? edge_tiles : 444;
    edge_kernel<<<grid2, 256, EDGE_SMEM_BYTES>>>(e_h, ext, src, dst, out, n_edges);
}